// round 13
// baseline (speedup 1.0000x reference)
#include <cuda_runtime.h>
#include <cuda_fp16.h>
#include <cstdint>

// Problem constants
#define IN_F     256
#define OUT_F    256
#define BATCH    512
#define NSEG     16
#define NT       49
#define KDIM     (IN_F * NT)        // 12544
#define KPAD     64                 // padded K per i-group
#define KDIM_PAD (IN_F * KPAD)      // 16384

#define I_SPLIT  37                 // grid = 4 * 37 = 148 CTAs = #SMs
#define M_TILE   128

// Static device scratch
__device__ __half g_wh[(size_t)OUT_F * KDIM_PAD];           // fp16 padded weights, 8.4 MB
__device__ float  g_part[(size_t)I_SPLIT * BATCH * OUT_F];  // partials [split][b][o], 19.4 MB

// ---------------------------------------------------------------------------
// helpers
// ---------------------------------------------------------------------------
__device__ __forceinline__ uint32_t smem_u32(const void* p) {
    uint32_t a;
    asm("{ .reg .u64 t; cvta.to.shared.u64 t, %1; cvt.u32.u64 %0, t; }" : "=r"(a) : "l"(p));
    return a;
}
__device__ __forceinline__ void ldsm_x4(uint32_t* r, uint32_t addr) {
    asm volatile("ldmatrix.sync.aligned.m8n8.x4.shared.b16 {%0,%1,%2,%3}, [%4];"
                 : "=r"(r[0]), "=r"(r[1]), "=r"(r[2]), "=r"(r[3]) : "r"(addr));
}
__device__ __forceinline__ void mma16816(float* c, const uint32_t* a,
                                         uint32_t b0, uint32_t b1) {
    asm volatile(
        "mma.sync.aligned.m16n8k16.row.col.f32.f16.f16.f32 "
        "{%0,%1,%2,%3}, {%4,%5,%6,%7}, {%8,%9}, {%0,%1,%2,%3};"
        : "+f"(c[0]), "+f"(c[1]), "+f"(c[2]), "+f"(c[3])
        : "r"(a[0]), "r"(a[1]), "r"(a[2]), "r"(a[3]), "r"(b0), "r"(b1));
}
__device__ __forceinline__ uint32_t sw128(uint32_t off) {
    return off ^ ((off >> 3) & 0x70);
}

// ---------------------------------------------------------------------------
// Kernel 1: repack w[o][i*49+t] fp32 -> g_wh[o][i*64+t] fp16, zero-padded.
// ---------------------------------------------------------------------------
__global__ __launch_bounds__(256) void repack_w(const float* __restrict__ w) {
    int idx = blockIdx.x * 256 + threadIdx.x;   // 256*256*16 total
    int t4   = idx & 15;
    int rest = idx >> 4;
    int i = rest & 255;
    int o = rest >> 8;
    int tb = t4 * 4;

    const float* src = w + (size_t)o * KDIM + i * NT;
    float v0 = (tb + 0 < NT) ? src[tb + 0] : 0.f;
    float v1 = (tb + 1 < NT) ? src[tb + 1] : 0.f;
    float v2 = (tb + 2 < NT) ? src[tb + 2] : 0.f;
    float v3 = (tb + 3 < NT) ? src[tb + 3] : 0.f;

    uint32_t u0 = (uint32_t)__half_as_ushort(__float2half_rn(v0))
                | ((uint32_t)__half_as_ushort(__float2half_rn(v1)) << 16);
    uint32_t u1 = (uint32_t)__half_as_ushort(__float2half_rn(v2))
                | ((uint32_t)__half_as_ushort(__float2half_rn(v3)) << 16);

    *(uint2*)(g_wh + (size_t)o * KDIM_PAD + i * KPAD + tb) = make_uint2(u0, u1);
}

// ---------------------------------------------------------------------------
// Kernel 2: mma.sync GEMM.  D[128,256] += A[128,64] * B[256,64]^T per i-group.
// A = basis tile built in-kernel (fp16, 4 nonzeros/row). B = g_wh rows (K-major).
// Grid (4, 37) = 148 CTAs. 512 threads = 8 M-warps x 2 N-warps.
// Warp tile: m16 x n128. Double-buffered smem + register prefetch.
// ---------------------------------------------------------------------------
#define SM_A0 0
#define SM_A1 16384
#define SM_B0 32768
#define SM_B1 65536
#define SM_TOTAL 98304

__global__ __launch_bounds__(512, 1) void pp_gemm(const float* __restrict__ x) {
    extern __shared__ char smem[];
    const uint32_t sb = smem_u32(smem);

    const int tid  = threadIdx.x;
    const int lane = tid & 31;
    const int wid  = tid >> 5;
    const int wm   = wid & 7;        // M position (8 x 16 rows)
    const int wn   = wid >> 3;       // N position (2 x 128 cols)
    const int bt0  = blockIdx.x * M_TILE;
    const int split = blockIdx.y;
    const int icnt = (split < 34) ? 7 : 6;
    const int i0   = (split < 34) ? split * 7 : 238 + (split - 34) * 6;

    float acc[16][4];
#pragma unroll
    for (int t = 0; t < 16; t++)
#pragma unroll
        for (int q = 0; q < 4; q++) acc[t][q] = 0.f;

    // prefetch registers
    uint4 br[4];
    unsigned short hb[4] = {0, 0, 0, 0};
    int w3 = 0;

    // global loads for i-group i -> registers
    auto loadg = [&](int i) {
#pragma unroll
        for (int p = 0; p < 4; p++) {
            const int e = tid + p * 512;                 // 0..2047
            const int o = e >> 3, part = e & 7;          // part: 16B unit in row
            br[p] = *(const uint4*)(g_wh + (size_t)o * KDIM_PAD + i * KPAD + part * 8);
        }
        if (tid < M_TILE) {
            const float xv = __ldg(x + (size_t)(bt0 + tid) * IN_F + i);
            int s = (int)((xv + 1.0f) * 0.5f * (float)NSEG);
            s = min(max(s, 0), NSEG - 1);
            const float xmin = (float)s * (2.0f / (float)NSEG) - 1.0f;
            const float xi   = (xv - xmin) * (float)NSEG - 1.0f;
            const float d0 = xi + 1.0f, d1 = xi + 0.5f, d2 = xi - 0.5f, d3 = xi - 1.0f;
            hb[0] = __half_as_ushort(__float2half_rn(d1 * d2 * d3 * (-1.0f / 1.5f)));
            hb[1] = __half_as_ushort(__float2half_rn(d0 * d2 * d3 * ( 1.0f / 0.75f)));
            hb[2] = __half_as_ushort(__float2half_rn(d0 * d1 * d3 * (-1.0f / 0.75f)));
            hb[3] = __half_as_ushort(__float2half_rn(d0 * d1 * d2 * ( 1.0f / 1.5f)));
            w3 = 3 * s;
        }
    };
    // registers -> smem buffers (swizzled)
    auto stores = [&](uint32_t aoff, uint32_t boff) {
#pragma unroll
        for (int p = 0; p < 4; p++) {
            const int e = tid + p * 512;
            const int o = e >> 3, part = e & 7;
            const uint32_t off = o * 128 + part * 16;
            *(uint4*)(smem + boff + sw128(off)) = br[p];
        }
        if (tid < M_TILE) {
            // zero own row (swizzle permutes 16B blocks within the row -> plain ok)
            const uint4 z = make_uint4(0, 0, 0, 0);
#pragma unroll
            for (int q = 0; q < 8; q++)
                *(uint4*)(smem + aoff + tid * 128 + q * 16) = z;
#pragma unroll
            for (int j = 0; j < 4; j++) {
                const uint32_t off = tid * 128 + (w3 + j) * 2;
                *(unsigned short*)(smem + aoff + sw128(off)) = hb[j];
            }
        }
    };

    loadg(i0);
    stores(SM_A0, SM_B0);
    __syncthreads();

    // A ldmatrix lane mapping: lanes 0-15 -> rows 0-15 @ col, 16-31 -> rows @ col+16B
    const int a_lr = lane & 15;
    const int a_lc = (lane >> 4) << 4;
    // B ldmatrix (no trans) lane mapping per x4 register order:
    //   lanes 0-7:   n-rows 0-7  @ col      (-> b0 of n-sub-block 0)
    //   lanes 8-15:  n-rows 0-7  @ col+16B  (-> b1 of n-sub-block 0)
    //   lanes 16-23: n-rows 8-15 @ col      (-> b0 of n-sub-block 1)
    //   lanes 24-31: n-rows 8-15 @ col+16B  (-> b1 of n-sub-block 1)
    const int b_r8 = lane & 7;
    const int b_radd = (lane >> 4) << 3;          // +8 rows for lanes 16-31
    const int b_cadd = ((lane >> 3) & 1) << 4;    // +16 bytes for groups 1 and 3

    for (int ii = 0; ii < icnt; ii++) {
        const uint32_t Ab = sb + ((ii & 1) ? SM_A1 : SM_A0);
        const uint32_t Bb = sb + ((ii & 1) ? SM_B1 : SM_B0);

        if (ii + 1 < icnt) loadg(i0 + ii + 1);   // overlap with MMA below

#pragma unroll
        for (int kk = 0; kk < 4; kk++) {
            const uint32_t kcol = kk * 32;       // 16 halfs = 32 bytes per k16 step
            uint32_t a[4];
            {
                const uint32_t off = (wm * 16 + a_lr) * 128 + kcol + a_lc;
                ldsm_x4(a, Ab + sw128(off));
            }
#pragma unroll
            for (int nt = 0; nt < 8; nt++) {
                uint32_t b[4];
                const uint32_t off = (wn * 128 + nt * 16 + b_radd + b_r8) * 128
                                     + kcol + b_cadd;
                ldsm_x4(b, Bb + sw128(off));
                mma16816(acc[2 * nt],     a, b[0], b[1]);
                mma16816(acc[2 * nt + 1], a, b[2], b[3]);
            }
        }
        __syncthreads();
        if (ii + 1 < icnt) {
            stores((ii & 1) ? SM_A0 : SM_A1, (ii & 1) ? SM_B0 : SM_B1);
            __syncthreads();
        }
    }

    // epilogue: c0,c1 -> (row lane/4, col 2*(lane%4)+{0,1}); c2,c3 -> row+8
    {
        float* dst = g_part + (size_t)split * (BATCH * OUT_F);
        const int r0 = bt0 + wm * 16 + (lane >> 2);
        const int cb = wn * 128 + (lane & 3) * 2;
#pragma unroll
        for (int nt = 0; nt < 16; nt++) {
            const int c = cb + nt * 8;
            *(float2*)(dst + (size_t)r0 * OUT_F + c)       = make_float2(acc[nt][0], acc[nt][1]);
            *(float2*)(dst + (size_t)(r0 + 8) * OUT_F + c) = make_float2(acc[nt][2], acc[nt][3]);
        }
    }
}

// ---------------------------------------------------------------------------
// Kernel 3: reduce the 37 i-split partials. Block = 512 threads =
// 64 outputs x 8 k-groups (5/5/5/5/5/4/4/4 partials each); fixed-order tree.
// Grid = 512 CTAs.
// ---------------------------------------------------------------------------
__global__ __launch_bounds__(512) void reduce_kernel(float* __restrict__ out) {
    __shared__ float4 sm[512];
    const int tid = threadIdx.x;
    const int o4  = blockIdx.x * 64 + (tid & 63);   // float4 index, 0..32767
    const int kg  = tid >> 6;                        // 0..7

    const int start = (kg < 5) ? kg * 5 : 25 + (kg - 5) * 4;
    const int cnt   = (kg < 5) ? 5 : 4;

    const float4* p = (const float4*)g_part + o4;
    float4 s = make_float4(0.f, 0.f, 0.f, 0.f);
#pragma unroll
    for (int k = 0; k < 5; k++) {
        if (k >= cnt) break;
        float4 v = __ldg(p + (size_t)(start + k) * (BATCH * OUT_F / 4));
        s.x += v.x; s.y += v.y; s.z += v.z; s.w += v.w;
    }
    sm[tid] = s;
    __syncthreads();

    if (kg < 2) {
        float4 a = sm[tid], b = sm[tid + 128], c = sm[tid + 256], d = sm[tid + 384];
        float4 r;
        r.x = ((a.x + b.x) + c.x) + d.x;
        r.y = ((a.y + b.y) + c.y) + d.y;
        r.z = ((a.z + b.z) + c.z) + d.z;
        r.w = ((a.w + b.w) + c.w) + d.w;
        sm[tid] = r;
    }
    __syncthreads();
    if (kg == 0) {
        float4 a = sm[tid], b = sm[tid + 64];
        float4 r;
        r.x = a.x + b.x; r.y = a.y + b.y; r.z = a.z + b.z; r.w = a.w + b.w;
        ((float4*)out)[o4] = r;
    }
}

// ---------------------------------------------------------------------------
extern "C" void kernel_launch(void* const* d_in, const int* in_sizes, int n_in,
                              void* d_out, int out_size) {
    const float* x = (const float*)d_in[0];   // [512, 256] f32
    const float* w = (const float*)d_in[1];   // [256, 256, 49] f32
    float* out = (float*)d_out;               // [512, 256] f32
    (void)in_sizes; (void)n_in; (void)out_size;

    // 1) repack weights to padded fp16
    repack_w<<<4096, 256>>>(w);

    // 2) HMMA GEMM into split-K partials
    cudaFuncSetAttribute(pp_gemm, cudaFuncAttributeMaxDynamicSharedMemorySize, SM_TOTAL);
    {
        dim3 grid(BATCH / M_TILE, I_SPLIT);   // (4, 37) = 148 CTAs
        pp_gemm<<<grid, 512, SM_TOTAL>>>(x);
    }

    // 3) reduce partials
    reduce_kernel<<<512, 512>>>(out);
}

// round 14
// speedup vs baseline: 1.0260x; 1.0260x over previous
#include <cuda_runtime.h>
#include <cuda_fp16.h>
#include <cstdint>

// Problem constants
#define IN_F     256
#define OUT_F    256
#define BATCH    512
#define NSEG     16
#define NT       49
#define KDIM     (IN_F * NT)        // 12544
#define KPAD     64                 // padded K per i-group
#define KDIM_PAD (IN_F * KPAD)      // 16384

#define I_SPLIT  37                 // grid = 4 * 37 = 148 CTAs = #SMs
#define I_MAX    7
#define M_TILE   128

// Static device scratch
__device__ __half g_wh[(size_t)OUT_F * KDIM_PAD];           // fp16 padded weights, 8.4 MB
__device__ float  g_part[(size_t)I_SPLIT * BATCH * OUT_F];  // partials [split][b][o], 19.4 MB

// ---------------------------------------------------------------------------
// helpers
// ---------------------------------------------------------------------------
__device__ __forceinline__ uint32_t smem_u32(const void* p) {
    uint32_t a;
    asm("{ .reg .u64 t; cvta.to.shared.u64 t, %1; cvt.u32.u64 %0, t; }" : "=r"(a) : "l"(p));
    return a;
}
__device__ __forceinline__ void ldsm_x4(uint32_t* r, uint32_t addr) {
    asm volatile("ldmatrix.sync.aligned.m8n8.x4.shared.b16 {%0,%1,%2,%3}, [%4];"
                 : "=r"(r[0]), "=r"(r[1]), "=r"(r[2]), "=r"(r[3]) : "r"(addr));
}
__device__ __forceinline__ void mma16816(float* c, const uint32_t* a,
                                         uint32_t b0, uint32_t b1) {
    asm volatile(
        "mma.sync.aligned.m16n8k16.row.col.f32.f16.f16.f32 "
        "{%0,%1,%2,%3}, {%4,%5,%6,%7}, {%8,%9}, {%0,%1,%2,%3};"
        : "+f"(c[0]), "+f"(c[1]), "+f"(c[2]), "+f"(c[3])
        : "r"(a[0]), "r"(a[1]), "r"(a[2]), "r"(a[3]), "r"(b0), "r"(b1));
}
__device__ __forceinline__ uint32_t sw128(uint32_t off) {
    return off ^ ((off >> 3) & 0x70);
}
__device__ __forceinline__ void cp_async16(uint32_t dst, const void* src) {
    asm volatile("cp.async.cg.shared.global [%0], [%1], 16;"
                 :: "r"(dst), "l"(src) : "memory");
}

// ---------------------------------------------------------------------------
// Kernel 1: repack w[o][i*49+t] fp32 -> g_wh[o][i*64+t] fp16, zero-padded.
// ---------------------------------------------------------------------------
__global__ __launch_bounds__(256) void repack_w(const float* __restrict__ w) {
    int idx = blockIdx.x * 256 + threadIdx.x;   // 256*256*16 total
    int t4   = idx & 15;
    int rest = idx >> 4;
    int i = rest & 255;
    int o = rest >> 8;
    int tb = t4 * 4;

    const float* src = w + (size_t)o * KDIM + i * NT;
    float v0 = (tb + 0 < NT) ? src[tb + 0] : 0.f;
    float v1 = (tb + 1 < NT) ? src[tb + 1] : 0.f;
    float v2 = (tb + 2 < NT) ? src[tb + 2] : 0.f;
    float v3 = (tb + 3 < NT) ? src[tb + 3] : 0.f;

    uint32_t u0 = (uint32_t)__half_as_ushort(__float2half_rn(v0))
                | ((uint32_t)__half_as_ushort(__float2half_rn(v1)) << 16);
    uint32_t u1 = (uint32_t)__half_as_ushort(__float2half_rn(v2))
                | ((uint32_t)__half_as_ushort(__float2half_rn(v3)) << 16);

    *(uint2*)(g_wh + (size_t)o * KDIM_PAD + i * KPAD + tb) = make_uint2(u0, u1);
}

// ---------------------------------------------------------------------------
// Kernel 2: mma.sync GEMM with cp.async double-buffered B.
// D[128,256] += A[128,64] * B[256,64]^T per i-group.
// Grid (4, 37) = 148 CTAs. 512 threads = 8 M-warps x 2 N-warps.
// ---------------------------------------------------------------------------
#define SM_A0 0
#define SM_A1 16384
#define SM_B0 32768
#define SM_B1 65536
#define SM_TOTAL 98304

__global__ __launch_bounds__(512, 1) void pp_gemm(const float* __restrict__ x) {
    extern __shared__ char smem[];
    const uint32_t sb = smem_u32(smem);

    const int tid  = threadIdx.x;
    const int lane = tid & 31;
    const int wid  = tid >> 5;
    const int wm   = wid & 7;        // M position (8 x 16 rows)
    const int wn   = wid >> 3;       // N position (2 x 128 cols)
    const int bt0  = blockIdx.x * M_TILE;
    const int split = blockIdx.y;
    const int icnt = (split < 34) ? 7 : 6;
    const int i0   = (split < 34) ? split * 7 : 238 + (split - 34) * 6;

    // --- precompute all basis fragments for this CTA's i-range (tid<128) ---
    unsigned short hbl[I_MAX][4];
    int w3l[I_MAX];
    if (tid < M_TILE) {
        const float* xrow = x + (size_t)(bt0 + tid) * IN_F + i0;
#pragma unroll
        for (int il = 0; il < I_MAX; il++) {
            if (il >= icnt) break;
            const float xv = __ldg(xrow + il);
            int s = (int)((xv + 1.0f) * 0.5f * (float)NSEG);
            s = min(max(s, 0), NSEG - 1);
            const float xmin = (float)s * (2.0f / (float)NSEG) - 1.0f;
            const float xi   = (xv - xmin) * (float)NSEG - 1.0f;
            const float d0 = xi + 1.0f, d1 = xi + 0.5f, d2 = xi - 0.5f, d3 = xi - 1.0f;
            hbl[il][0] = __half_as_ushort(__float2half_rn(d1 * d2 * d3 * (-1.0f / 1.5f)));
            hbl[il][1] = __half_as_ushort(__float2half_rn(d0 * d2 * d3 * ( 1.0f / 0.75f)));
            hbl[il][2] = __half_as_ushort(__float2half_rn(d0 * d1 * d3 * (-1.0f / 0.75f)));
            hbl[il][3] = __half_as_ushort(__float2half_rn(d0 * d1 * d2 * ( 1.0f / 1.5f)));
            w3l[il] = 3 * s;
        }
    }

    // cp.async B tile for i-group i into buffer boff
    auto cpB = [&](int i, uint32_t boff) {
#pragma unroll
        for (int p = 0; p < 4; p++) {
            const int e = tid + p * 512;                 // 0..2047
            const int o = e >> 3, part = e & 7;
            const uint32_t off = o * 128 + part * 16;
            cp_async16(sb + boff + sw128(off),
                       g_wh + (size_t)o * KDIM_PAD + i * KPAD + part * 8);
        }
        asm volatile("cp.async.commit_group;" ::: "memory");
    };
    // A-fill from precomputed fragments (tid<128)
    auto fillA = [&](int il, uint32_t aoff) {
        if (tid < M_TILE) {
            const uint4 z = make_uint4(0, 0, 0, 0);
#pragma unroll
            for (int q = 0; q < 8; q++)
                *(uint4*)(smem + aoff + tid * 128 + q * 16) = z;
            const int w3 = w3l[il];
#pragma unroll
            for (int j = 0; j < 4; j++) {
                const uint32_t off = tid * 128 + (w3 + j) * 2;
                *(unsigned short*)(smem + aoff + sw128(off)) = hbl[il][j];
            }
        }
    };

    float acc[16][4];
#pragma unroll
    for (int t = 0; t < 16; t++)
#pragma unroll
        for (int q = 0; q < 4; q++) acc[t][q] = 0.f;

    // prologue: fill buffer 0
    cpB(i0, SM_B0);
    fillA(0, SM_A0);
    asm volatile("cp.async.wait_group 0;" ::: "memory");
    __syncthreads();

    // ldmatrix lane mappings
    const int a_lr = lane & 15;
    const int a_lc = (lane >> 4) << 4;
    const int b_r8 = lane & 7;
    const int b_radd = (lane >> 4) << 3;
    const int b_cadd = ((lane >> 3) & 1) << 4;

    for (int ii = 0; ii < icnt; ii++) {
        const uint32_t Ab = sb + ((ii & 1) ? SM_A1 : SM_A0);
        const uint32_t Bb = sb + ((ii & 1) ? SM_B1 : SM_B0);

        if (ii + 1 < icnt) {
            cpB(i0 + ii + 1, (ii & 1) ? SM_B0 : SM_B1);
            fillA(ii + 1, (ii & 1) ? SM_A0 : SM_A1);
        }

#pragma unroll
        for (int kk = 0; kk < 4; kk++) {
            const uint32_t kcol = kk * 32;
            uint32_t a[4];
            {
                const uint32_t off = (wm * 16 + a_lr) * 128 + kcol + a_lc;
                ldsm_x4(a, Ab + sw128(off));
            }
#pragma unroll
            for (int nt = 0; nt < 8; nt++) {
                uint32_t b[4];
                const uint32_t off = (wn * 128 + nt * 16 + b_radd + b_r8) * 128
                                     + kcol + b_cadd;
                ldsm_x4(b, Bb + sw128(off));
                mma16816(acc[2 * nt],     a, b[0], b[1]);
                mma16816(acc[2 * nt + 1], a, b[2], b[3]);
            }
        }

        if (ii + 1 < icnt) {
            asm volatile("cp.async.wait_group 0;" ::: "memory");
        }
        __syncthreads();
    }

    // epilogue: c0,c1 -> (row lane/4, col 2*(lane%4)+{0,1}); c2,c3 -> row+8
    {
        float* dst = g_part + (size_t)split * (BATCH * OUT_F);
        const int r0 = bt0 + wm * 16 + (lane >> 2);
        const int cb = wn * 128 + (lane & 3) * 2;
#pragma unroll
        for (int nt = 0; nt < 16; nt++) {
            const int c = cb + nt * 8;
            *(float2*)(dst + (size_t)r0 * OUT_F + c)       = make_float2(acc[nt][0], acc[nt][1]);
            *(float2*)(dst + (size_t)(r0 + 8) * OUT_F + c) = make_float2(acc[nt][2], acc[nt][3]);
        }
    }
}

// ---------------------------------------------------------------------------
// Kernel 3: reduce the 37 i-split partials (fixed-order tree). Grid 512 x 512thr.
// ---------------------------------------------------------------------------
__global__ __launch_bounds__(512) void reduce_kernel(float* __restrict__ out) {
    __shared__ float4 sm[512];
    const int tid = threadIdx.x;
    const int o4  = blockIdx.x * 64 + (tid & 63);
    const int kg  = tid >> 6;

    const int start = (kg < 5) ? kg * 5 : 25 + (kg - 5) * 4;
    const int cnt   = (kg < 5) ? 5 : 4;

    const float4* p = (const float4*)g_part + o4;
    float4 s = make_float4(0.f, 0.f, 0.f, 0.f);
#pragma unroll
    for (int k = 0; k < 5; k++) {
        if (k >= cnt) break;
        float4 v = __ldg(p + (size_t)(start + k) * (BATCH * OUT_F / 4));
        s.x += v.x; s.y += v.y; s.z += v.z; s.w += v.w;
    }
    sm[tid] = s;
    __syncthreads();

    if (kg < 2) {
        float4 a = sm[tid], b = sm[tid + 128], c = sm[tid + 256], d = sm[tid + 384];
        float4 r;
        r.x = ((a.x + b.x) + c.x) + d.x;
        r.y = ((a.y + b.y) + c.y) + d.y;
        r.z = ((a.z + b.z) + c.z) + d.z;
        r.w = ((a.w + b.w) + c.w) + d.w;
        sm[tid] = r;
    }
    __syncthreads();
    if (kg == 0) {
        float4 a = sm[tid], b = sm[tid + 64];
        float4 r;
        r.x = a.x + b.x; r.y = a.y + b.y; r.z = a.z + b.z; r.w = a.w + b.w;
        ((float4*)out)[o4] = r;
    }
}

// ---------------------------------------------------------------------------
extern "C" void kernel_launch(void* const* d_in, const int* in_sizes, int n_in,
                              void* d_out, int out_size) {
    const float* x = (const float*)d_in[0];   // [512, 256] f32
    const float* w = (const float*)d_in[1];   // [256, 256, 49] f32
    float* out = (float*)d_out;               // [512, 256] f32
    (void)in_sizes; (void)n_in; (void)out_size;

    // 1) repack weights to padded fp16
    repack_w<<<4096, 256>>>(w);

    // 2) HMMA GEMM into split-K partials
    cudaFuncSetAttribute(pp_gemm, cudaFuncAttributeMaxDynamicSharedMemorySize, SM_TOTAL);
    {
        dim3 grid(BATCH / M_TILE, I_SPLIT);   // (4, 37) = 148 CTAs
        pp_gemm<<<grid, 512, SM_TOTAL>>>(x);
    }

    // 3) reduce partials
    reduce_kernel<<<512, 512>>>(out);
}

// round 15
// speedup vs baseline: 1.1653x; 1.1358x over previous
#include <cuda_runtime.h>
#include <cuda_fp16.h>
#include <cstdint>

// Problem constants
#define IN_F     256
#define OUT_F    256
#define BATCH    512
#define NSEG     16
#define NT       49
#define KDIM     (IN_F * NT)        // 12544 (native K, no padding)
#define NCHUNK   (KDIM / 16)        // 784 chunks of 16 halfs

#define I_SPLIT  37                 // grid = 4 * 37 = 148 CTAs = #SMs
#define M_TILE   128
#define NSLAB    6                  // slabs of <=4 chunks per split

// Static device scratch
__device__ __half g_wh[(size_t)OUT_F * KDIM];               // fp16 weights, native layout, 6.4 MB
__device__ float  g_part[(size_t)I_SPLIT * BATCH * OUT_F];  // partials [split][b][o], 19.4 MB

// ---------------------------------------------------------------------------
// helpers
// ---------------------------------------------------------------------------
__device__ __forceinline__ uint32_t smem_u32(const void* p) {
    uint32_t a;
    asm("{ .reg .u64 t; cvta.to.shared.u64 t, %1; cvt.u32.u64 %0, t; }" : "=r"(a) : "l"(p));
    return a;
}
__device__ __forceinline__ void ldsm_x4(uint32_t* r, uint32_t addr) {
    asm volatile("ldmatrix.sync.aligned.m8n8.x4.shared.b16 {%0,%1,%2,%3}, [%4];"
                 : "=r"(r[0]), "=r"(r[1]), "=r"(r[2]), "=r"(r[3]) : "r"(addr));
}
__device__ __forceinline__ void mma16816(float* c, const uint32_t* a,
                                         uint32_t b0, uint32_t b1) {
    asm volatile(
        "mma.sync.aligned.m16n8k16.row.col.f32.f16.f16.f32 "
        "{%0,%1,%2,%3}, {%4,%5,%6,%7}, {%8,%9}, {%0,%1,%2,%3};"
        : "+f"(c[0]), "+f"(c[1]), "+f"(c[2]), "+f"(c[3])
        : "r"(a[0]), "r"(a[1]), "r"(a[2]), "r"(a[3]), "r"(b0), "r"(b1));
}
__device__ __forceinline__ uint32_t sw128(uint32_t off) {
    return off ^ ((off >> 3) & 0x70);
}
__device__ __forceinline__ void cp_async16(uint32_t dst, const void* src) {
    asm volatile("cp.async.cg.shared.global [%0], [%1], 16;"
                 :: "r"(dst), "l"(src) : "memory");
}

// ---------------------------------------------------------------------------
// Kernel 1: fp32 -> fp16 convert, layout preserved. 802816 threads x 4 elems.
// ---------------------------------------------------------------------------
__global__ __launch_bounds__(256) void convert_w(const float* __restrict__ w) {
    const int idx = blockIdx.x * 256 + threadIdx.x;       // 0..802815
    float4 v = __ldg((const float4*)w + idx);
    uint32_t u0 = (uint32_t)__half_as_ushort(__float2half_rn(v.x))
                | ((uint32_t)__half_as_ushort(__float2half_rn(v.y)) << 16);
    uint32_t u1 = (uint32_t)__half_as_ushort(__float2half_rn(v.z))
                | ((uint32_t)__half_as_ushort(__float2half_rn(v.w)) << 16);
    *(uint2*)(g_wh + (size_t)idx * 4) = make_uint2(u0, u1);
}

// ---------------------------------------------------------------------------
// Kernel 2: mma.sync GEMM over NATIVE K (no padding).
// D[128,256] += A[128,K] * B[256,K]^T, K split at 16-half chunk granularity.
// A = sparse basis (built in-kernel; boundary-straddling nonzeros written
// partially by each split -- sum over splits is exact).
// Grid (4, 37) = 148 CTAs. 512 threads = 4 M-warps x 4 N-warps (m32 x n64).
// ---------------------------------------------------------------------------
#define SM_A0 0
#define SM_A1 16384
#define SM_B0 32768
#define SM_B1 65536
#define SM_TOTAL 98304

__global__ __launch_bounds__(512, 1) void pp_gemm(const float* __restrict__ x) {
    extern __shared__ char smem[];
    const uint32_t sb = smem_u32(smem);

    const int tid  = threadIdx.x;
    const int lane = tid & 31;
    const int wid  = tid >> 5;
    const int wm   = wid & 3;        // M position (4 x 32 rows)
    const int wn   = wid >> 2;       // N position (4 x 64 cols)
    const int bt0  = blockIdx.x * M_TILE;
    const int split = blockIdx.y;

    // chunk range for this split: 0..6 -> 22 chunks, 7..36 -> 21 (total 784)
    const int nch = (split < 7) ? 22 : 21;
    const int c0  = (split < 7) ? split * 22 : 154 + (split - 7) * 21;

    // B slab copy: chunks [cc, cc+nk) -> boff. 2 threads per o-row.
    auto cpB = [&](int cc, int nk, uint32_t boff) {
        const int o = tid >> 1;
        const __half* src = g_wh + (size_t)o * KDIM + cc * 16;
#pragma unroll 4
        for (int p = 0; p < nk; p++) {
            const int part = (tid & 1) + 2 * p;          // 0..2nk-1
            const uint32_t off = o * 128 + part * 16;
            cp_async16(sb + boff + sw128(off), src + part * 8);
        }
        asm volatile("cp.async.commit_group;" ::: "memory");
    };
    // A fill for k-range [k0, k0 + nk*16): zero row, write in-range nonzeros.
    auto fillA = [&](int k0, int nk, uint32_t aoff) {
        if (tid < M_TILE) {
            const uint4 z = make_uint4(0, 0, 0, 0);
#pragma unroll
            for (int q = 0; q < 8; q++)
                *(uint4*)(smem + aoff + tid * 128 + q * 16) = z;

            const int kend = k0 + nk * 16;
            const int i_lo = k0 / NT;
            const int i_hi = (kend - 1) / NT;
            for (int i = i_lo; i <= i_hi; i++) {
                const float xv = __ldg(x + (size_t)(bt0 + tid) * IN_F + i);
                int s = (int)((xv + 1.0f) * 0.5f * (float)NSEG);
                s = min(max(s, 0), NSEG - 1);
                const float xmin = (float)s * (2.0f / (float)NSEG) - 1.0f;
                const float xi   = (xv - xmin) * (float)NSEG - 1.0f;
                const float d0 = xi + 1.0f, d1 = xi + 0.5f, d2 = xi - 0.5f, d3 = xi - 1.0f;
                unsigned short h[4];
                h[0] = __half_as_ushort(__float2half_rn(d1 * d2 * d3 * (-1.0f / 1.5f)));
                h[1] = __half_as_ushort(__float2half_rn(d0 * d2 * d3 * ( 1.0f / 0.75f)));
                h[2] = __half_as_ushort(__float2half_rn(d0 * d1 * d3 * (-1.0f / 0.75f)));
                h[3] = __half_as_ushort(__float2half_rn(d0 * d1 * d2 * ( 1.0f / 1.5f)));
                const int kbase = i * NT + 3 * s;
#pragma unroll
                for (int j = 0; j < 4; j++) {
                    const int k = kbase + j;
                    if (k >= k0 && k < kend) {
                        const uint32_t off = tid * 128 + (k - k0) * 2;
                        *(unsigned short*)(smem + aoff + sw128(off)) = h[j];
                    }
                }
            }
        }
    };

    float acc[2][8][4];
#pragma unroll
    for (int mt = 0; mt < 2; mt++)
#pragma unroll
        for (int nt = 0; nt < 8; nt++)
#pragma unroll
            for (int q = 0; q < 4; q++) acc[mt][nt][q] = 0.f;

    // prologue: slab 0 (always 4 chunks)
    cpB(c0, 4, SM_B0);
    fillA(c0 * 16, 4, SM_A0);
    asm volatile("cp.async.wait_group 0;" ::: "memory");
    __syncthreads();

    // ldmatrix lane mappings
    const int a_lr = lane & 15;
    const int a_lc = (lane >> 4) << 4;
    const int b_r8 = lane & 7;
    const int b_radd = (lane >> 4) << 3;
    const int b_cadd = ((lane >> 3) & 1) << 4;

    for (int sl = 0; sl < NSLAB; sl++) {
        const uint32_t Ab = sb + ((sl & 1) ? SM_A1 : SM_A0);
        const uint32_t Bb = sb + ((sl & 1) ? SM_B1 : SM_B0);
        const int nk = min(4, nch - 4 * sl);

        if (sl + 1 < NSLAB) {
            const int cc2 = c0 + 4 * (sl + 1);
            const int nk2 = min(4, nch - 4 * (sl + 1));
            cpB(cc2, nk2, (sl & 1) ? SM_B0 : SM_B1);
            fillA(cc2 * 16, nk2, (sl & 1) ? SM_A0 : SM_A1);
        }

        for (int kk = 0; kk < nk; kk++) {
            const uint32_t kcol = kk * 32;
            uint32_t a[2][4];
#pragma unroll
            for (int mt = 0; mt < 2; mt++) {
                const uint32_t off = (wm * 32 + mt * 16 + a_lr) * 128 + kcol + a_lc;
                ldsm_x4(a[mt], Ab + sw128(off));
            }
#pragma unroll
            for (int g = 0; g < 4; g++) {
                uint32_t b[4];
                const uint32_t off = (wn * 64 + g * 16 + b_radd + b_r8) * 128
                                     + kcol + b_cadd;
                ldsm_x4(b, Bb + sw128(off));
#pragma unroll
                for (int mt = 0; mt < 2; mt++) {
                    mma16816(acc[mt][2 * g],     a[mt], b[0], b[1]);
                    mma16816(acc[mt][2 * g + 1], a[mt], b[2], b[3]);
                }
            }
        }

        if (sl + 1 < NSLAB) {
            asm volatile("cp.async.wait_group 0;" ::: "memory");
        }
        __syncthreads();
    }

    // epilogue: c0,c1 -> (row lane/4, col 2*(lane%4)+{0,1}); c2,c3 -> row+8
    {
        float* dst = g_part + (size_t)split * (BATCH * OUT_F);
        const int cb = wn * 64 + (lane & 3) * 2;
#pragma unroll
        for (int mt = 0; mt < 2; mt++) {
            const int r0 = bt0 + wm * 32 + mt * 16 + (lane >> 2);
#pragma unroll
            for (int nt = 0; nt < 8; nt++) {
                const int c = cb + nt * 8;
                *(float2*)(dst + (size_t)r0 * OUT_F + c) =
                    make_float2(acc[mt][nt][0], acc[mt][nt][1]);
                *(float2*)(dst + (size_t)(r0 + 8) * OUT_F + c) =
                    make_float2(acc[mt][nt][2], acc[mt][nt][3]);
            }
        }
    }
}

// ---------------------------------------------------------------------------
// Kernel 3: reduce the 37 i-split partials (fixed-order tree). Grid 512 x 512thr.
// ---------------------------------------------------------------------------
__global__ __launch_bounds__(512) void reduce_kernel(float* __restrict__ out) {
    __shared__ float4 sm[512];
    const int tid = threadIdx.x;
    const int o4  = blockIdx.x * 64 + (tid & 63);
    const int kg  = tid >> 6;

    const int start = (kg < 5) ? kg * 5 : 25 + (kg - 5) * 4;
    const int cnt   = (kg < 5) ? 5 : 4;

    const float4* p = (const float4*)g_part + o4;
    float4 s = make_float4(0.f, 0.f, 0.f, 0.f);
#pragma unroll
    for (int k = 0; k < 5; k++) {
        if (k >= cnt) break;
        float4 v = __ldg(p + (size_t)(start + k) * (BATCH * OUT_F / 4));
        s.x += v.x; s.y += v.y; s.z += v.z; s.w += v.w;
    }
    sm[tid] = s;
    __syncthreads();

    if (kg < 2) {
        float4 a = sm[tid], b = sm[tid + 128], c = sm[tid + 256], d = sm[tid + 384];
        float4 r;
        r.x = ((a.x + b.x) + c.x) + d.x;
        r.y = ((a.y + b.y) + c.y) + d.y;
        r.z = ((a.z + b.z) + c.z) + d.z;
        r.w = ((a.w + b.w) + c.w) + d.w;
        sm[tid] = r;
    }
    __syncthreads();
    if (kg == 0) {
        float4 a = sm[tid], b = sm[tid + 64];
        float4 r;
        r.x = a.x + b.x; r.y = a.y + b.y; r.z = a.z + b.z; r.w = a.w + b.w;
        ((float4*)out)[o4] = r;
    }
}

// ---------------------------------------------------------------------------
extern "C" void kernel_launch(void* const* d_in, const int* in_sizes, int n_in,
                              void* d_out, int out_size) {
    const float* x = (const float*)d_in[0];   // [512, 256] f32
    const float* w = (const float*)d_in[1];   // [256, 256, 49] f32
    float* out = (float*)d_out;               // [512, 256] f32
    (void)in_sizes; (void)n_in; (void)out_size;

    // 1) fp32 -> fp16 convert (layout preserved)
    convert_w<<<3136, 256>>>(w);

    // 2) HMMA GEMM over native K into split-K partials
    cudaFuncSetAttribute(pp_gemm, cudaFuncAttributeMaxDynamicSharedMemorySize, SM_TOTAL);
    {
        dim3 grid(BATCH / M_TILE, I_SPLIT);   // (4, 37) = 148 CTAs
        pp_gemm<<<grid, 512, SM_TOTAL>>>(x);
    }

    // 3) reduce partials
    reduce_kernel<<<512, 512>>>(out);
}